// round 1
// baseline (speedup 1.0000x reference)
#include <cuda_runtime.h>
#include <math.h>

#define NBLK  2048
#define NTHR  256
#define NWARP (NTHR / 32)
#define K2THR 512

// Per-class chain monoid over a contiguous row segment:
// f = sign of first row of this class in segment (0 if none)
// l = sign of last  row of this class in segment (0 if none)
// S = sum of sign(a)*sign(b) over consecutive same-class pairs inside segment
struct Chain { int f0, l0, S0, f1, l1, S1; };

__device__ __forceinline__ Chain chain_combine(const Chain& a, const Chain& b) {
    Chain r;
    r.S0 = a.S0 + b.S0 + a.l0 * b.f0;   // product is 0 if either side empty
    r.S1 = a.S1 + b.S1 + a.l1 * b.f1;
    r.f0 = a.f0 ? a.f0 : b.f0;
    r.f1 = a.f1 ? a.f1 : b.f1;
    r.l0 = b.l0 ? b.l0 : a.l0;
    r.l1 = b.l1 ? b.l1 : a.l1;
    return r;
}

__device__ double    g_ldam[NBLK];
__device__ double    g_focal[NBLK];
__device__ long long g_n1[NBLK];
__device__ int       g_mon[NBLK][6];

__device__ __forceinline__ void row_op(float x0, float x1, int t, float c30_1,
                                       float& lsum, float& fsum, int& n1c, Chain& ch)
{
    float d  = x0 - x1;
    bool  t1 = (t != 0);

    // LDAM: nll = softplus(30*(x_other - x_target + m_target))
    // t==0: a = 30*(0.5 - d) ; t==1: a = 30*(d + m1)
    float sd  = t1 ? d : -d;
    float c30 = t1 ? c30_1 : 15.0f;
    float a   = fmaf(30.0f, sd, c30);
    float e   = __expf(-fabsf(a));
    float nll = fmaxf(a, 0.0f) + __logf(1.0f + e);
    float w   = t1 ? 0.85f : 0.15f;
    lsum = fmaf(w, nll, lsum);

    // Focal: w * (1-la)^2 * (-log(la + eps)), la = t ? p : 1-p, p = x1
    float la   = t1 ? x1 : (1.0f - x1);
    float omla = 1.0f - la;
    float sq   = omla * omla;
    float lg   = __logf(la + 1e-9f);
    fsum = fmaf(w * sq, -lg, fsum);

    n1c += (int)t1;

    // Chain append: sign of d, routed to the row's class
    int s  = (d > 0.0f) ? 1 : -1;
    int s0 = t1 ? 0 : s;
    int s1 = t1 ? s : 0;
    ch.S0 += ch.l0 * s0;
    ch.f0  = ch.f0 ? ch.f0 : s0;
    ch.l0  = s0 ? s0 : ch.l0;
    ch.S1 += ch.l1 * s1;
    ch.f1  = ch.f1 ? ch.f1 : s1;
    ch.l1  = s1 ? s1 : ch.l1;
}

__global__ __launch_bounds__(NTHR) void pass1(
    const float* __restrict__ x, const int* __restrict__ tg,
    int B, int rpw, float c30_1)
{
    int lane = threadIdx.x & 31;
    int warp = threadIdx.x >> 5;
    // Each warp owns a contiguous strip of rpw rows; blocks are contiguous in order.
    long long wbase_ll = (long long)blockIdx.x * ((long long)rpw * NWARP) + (long long)warp * rpw;
    const float4* x4 = (const float4*)x;
    const int4*   t4 = (const int4*)tg;

    float lsum = 0.f, fsum = 0.f;
    int n1 = 0;
    Chain wacc = {0, 0, 0, 0, 0, 0};

    int iters = (rpw + 127) >> 7;   // 128 rows per warp-iteration
    for (int j = 0; j < iters; ++j) {
        long long row_ll = wbase_ll + (long long)j * 128 + lane * 4;
        Chain seg = {0, 0, 0, 0, 0, 0};
        if (row_ll + 3 < (long long)B) {
            int row = (int)row_ll;
            float4 xa = x4[row >> 1];          // rows row, row+1
            float4 xb = x4[(row >> 1) + 1];    // rows row+2, row+3
            int4   tt = t4[row >> 2];
            row_op(xa.x, xa.y, tt.x, c30_1, lsum, fsum, n1, seg);
            row_op(xa.z, xa.w, tt.y, c30_1, lsum, fsum, n1, seg);
            row_op(xb.x, xb.y, tt.z, c30_1, lsum, fsum, n1, seg);
            row_op(xb.z, xb.w, tt.w, c30_1, lsum, fsum, n1, seg);
        } else if (row_ll < (long long)B) {
            for (int k = 0; k < 4; ++k) {
                long long r = row_ll + k;
                if (r < (long long)B)
                    row_op(x[2 * r], x[2 * r + 1], tg[r], c30_1, lsum, fsum, n1, seg);
            }
        }
        // Ordered (non-commutative) warp tree reduce of the 32 lane segments.
        #pragma unroll
        for (int off = 1; off < 32; off <<= 1) {
            Chain o;
            o.f0 = __shfl_down_sync(0xffffffffu, seg.f0, off);
            o.l0 = __shfl_down_sync(0xffffffffu, seg.l0, off);
            o.S0 = __shfl_down_sync(0xffffffffu, seg.S0, off);
            o.f1 = __shfl_down_sync(0xffffffffu, seg.f1, off);
            o.l1 = __shfl_down_sync(0xffffffffu, seg.l1, off);
            o.S1 = __shfl_down_sync(0xffffffffu, seg.S1, off);
            if (lane + off < 32) seg = chain_combine(seg, o);
        }
        if (lane == 0) wacc = chain_combine(wacc, seg);   // warp iters are contiguous
    }

    // Commutative scalar reductions across the warp.
    #pragma unroll
    for (int off = 16; off; off >>= 1) {
        lsum += __shfl_down_sync(0xffffffffu, lsum, off);
        fsum += __shfl_down_sync(0xffffffffu, fsum, off);
        n1   += __shfl_down_sync(0xffffffffu, n1, off);
    }

    __shared__ Chain smon[NWARP];
    __shared__ float sls[NWARP], sfs[NWARP];
    __shared__ int   sn1[NWARP];
    if (lane == 0) { smon[warp] = wacc; sls[warp] = lsum; sfs[warp] = fsum; sn1[warp] = n1; }
    __syncthreads();
    if (threadIdx.x == 0) {
        Chain c = smon[0];
        double dl = (double)sls[0], df = (double)sfs[0];
        long long nn = sn1[0];
        for (int w = 1; w < NWARP; ++w) {   // warps are in row order
            c = chain_combine(c, smon[w]);
            dl += (double)sls[w]; df += (double)sfs[w]; nn += sn1[w];
        }
        g_ldam[blockIdx.x]  = dl;
        g_focal[blockIdx.x] = df;
        g_n1[blockIdx.x]    = nn;
        int* m = g_mon[blockIdx.x];
        m[0] = c.f0; m[1] = c.l0; m[2] = c.S0;
        m[3] = c.f1; m[4] = c.l1; m[5] = c.S1;
    }
}

__global__ __launch_bounds__(K2THR) void pass2(float* out, long long B)
{
    int tid = threadIdx.x;
    const int chunk = NBLK / K2THR;   // 4 consecutive block-partials per thread
    Chain c = {0, 0, 0, 0, 0, 0};
    double dl = 0.0, df = 0.0;
    long long nn = 0;
    for (int k = 0; k < chunk; ++k) {
        int i = tid * chunk + k;      // in block order
        const int* m = g_mon[i];
        Chain b = {m[0], m[1], m[2], m[3], m[4], m[5]};
        c = chain_combine(c, b);
        dl += g_ldam[i]; df += g_focal[i]; nn += g_n1[i];
    }

    __shared__ int       sm[6][K2THR];
    __shared__ double    sdl[K2THR], sdf[K2THR];
    __shared__ long long snn[K2THR];
    sm[0][tid] = c.f0; sm[1][tid] = c.l0; sm[2][tid] = c.S0;
    sm[3][tid] = c.f1; sm[4][tid] = c.l1; sm[5][tid] = c.S1;
    sdl[tid] = dl; sdf[tid] = df; snn[tid] = nn;

    for (int off = 1; off < K2THR; off <<= 1) {
        __syncthreads();
        if ((tid & (2 * off - 1)) == 0) {
            int j = tid + off;
            Chain a2 = {sm[0][tid], sm[1][tid], sm[2][tid], sm[3][tid], sm[4][tid], sm[5][tid]};
            Chain b2 = {sm[0][j],   sm[1][j],   sm[2][j],   sm[3][j],   sm[4][j],   sm[5][j]};
            Chain r  = chain_combine(a2, b2);
            sm[0][tid] = r.f0; sm[1][tid] = r.l0; sm[2][tid] = r.S0;
            sm[3][tid] = r.f1; sm[4][tid] = r.l1; sm[5][tid] = r.S1;
            sdl[tid] += sdl[j]; sdf[tid] += sdf[j]; snn[tid] += snn[j];
        }
    }
    __syncthreads();

    if (tid == 0) {
        long long n1 = snn[0];
        long long n0 = B - n1;
        double W     = 0.15 * (double)n0 + 0.85 * (double)n1;
        double ldam  = sdl[0] / W;
        double focal = sdf[0] / (double)B;
        double p0 = (n0 > 0) ? (double)sm[2][0] / (double)n0 : 0.0;
        double p1 = (n1 > 0) ? (double)sm[5][0] / (double)n1 : 0.0;
        double dp = p0 - p1;
        out[0] = (float)(ldam + focal + dp * dp);
    }
}

extern "C" void kernel_launch(void* const* d_in, const int* in_sizes, int n_in,
                              void* d_out, int out_size)
{
    const float* x  = (const float*)d_in[0];
    const int*   tg = (const int*)d_in[1];
    int B = in_sizes[1];                       // number of rows (targets)

    // rows per warp, multiple of 128 (one warp-iteration)
    int rpw = (B + NBLK * NWARP - 1) / (NBLK * NWARP);
    rpw = (rpw + 127) & ~127;

    // m1' = 0.5 * (85/900)^0.25 (class-1 LDAM margin), pre-scaled by 30
    float c30_1 = (float)(30.0 * 0.5 * pow(85.0 / 900.0, 0.25));

    pass1<<<NBLK, NTHR>>>(x, tg, B, rpw, c30_1);
    pass2<<<1, K2THR>>>((float*)d_out, (long long)B);
}

// round 2
// speedup vs baseline: 1.1483x; 1.1483x over previous
#include <cuda_runtime.h>
#include <math.h>

#define GRID  592            // 148 SMs * 4 blocks -> exactly one wave at 256thr/64reg
#define NTHR  256
#define NWARP (NTHR / 32)

// Per-class chain monoid over a contiguous row segment:
// f = sign of first row of this class in segment (0 if none)
// l = sign of last  row of this class in segment (0 if none)
// S = sum of sign(a)*sign(b) over consecutive same-class pairs inside segment
struct Chain { int f0, l0, S0, f1, l1, S1; };

__device__ __forceinline__ Chain chain_combine(const Chain& a, const Chain& b) {
    Chain r;
    r.S0 = a.S0 + b.S0 + a.l0 * b.f0;
    r.S1 = a.S1 + b.S1 + a.l1 * b.f1;
    r.f0 = a.f0 ? a.f0 : b.f0;
    r.f1 = a.f1 ? a.f1 : b.f1;
    r.l0 = b.l0 ? b.l0 : a.l0;
    r.l1 = b.l1 ? b.l1 : a.l1;
    return r;
}

// Ballot-based ordered combine of 32 lane-chains (one class) in a single step.
// Empty lanes (f==0) are skipped exactly as the monoid prescribes.
__device__ __forceinline__ void warp_chain(int f, int l, int S, int lane,
                                           int& Fw, int& Lw, int& Sw)
{
    unsigned m     = __ballot_sync(0xffffffffu, f != 0);
    unsigned below = m & ((1u << lane) - 1u);
    int prev_l = __shfl_sync(0xffffffffu, l, below ? (31 - __clz(below)) : 0);
    int term   = (f != 0 && below) ? prev_l * f : 0;
    Sw = __reduce_add_sync(0xffffffffu, S + term);
    int fsrc = m ? (__ffs(m) - 1) : 0;
    int lsrc = m ? (31 - __clz(m)) : 0;
    Fw = __shfl_sync(0xffffffffu, f, fsrc);
    Lw = __shfl_sync(0xffffffffu, l, lsrc);
    if (!m) { Fw = 0; Lw = 0; }
}

__device__ float    g_l[GRID];
__device__ float    g_f[GRID];
__device__ int      g_n1[GRID];
__device__ int      g_c[GRID][6];
__device__ unsigned g_count = 0;   // reset to 0 by last block each run (replay-safe)

__device__ __forceinline__ void row_op(float x0, float x1, int t, float c30_1,
                                       float& lsum, float& fsum, int& n1c, Chain& ch)
{
    float d  = x0 - x1;
    bool  t1 = (t != 0);

    // LDAM: nll = softplus(30*(x_other - x_target + m_target))
    float sd  = t1 ? d : -d;
    float c30 = t1 ? c30_1 : 15.0f;
    float a   = fmaf(30.0f, sd, c30);
    float e   = __expf(-fabsf(a));
    float nll = fmaxf(a, 0.0f) + __logf(1.0f + e);
    float w   = t1 ? 0.85f : 0.15f;
    lsum = fmaf(w, nll, lsum);

    // Focal: w * (1-la)^2 * (-log(la + eps)), la = t ? p : 1-p, p = x1
    float la   = t1 ? x1 : (1.0f - x1);
    float omla = 1.0f - la;
    float sq   = omla * omla;
    float lg   = __logf(la + 1e-9f);
    fsum = fmaf(w * sq, -lg, fsum);

    n1c += (int)t1;

    // Chain append: sign of d, routed to the row's class
    int s  = (d > 0.0f) ? 1 : -1;
    int s0 = t1 ? 0 : s;
    int s1 = t1 ? s : 0;
    ch.S0 += ch.l0 * s0;
    ch.f0  = ch.f0 ? ch.f0 : s0;
    ch.l0  = s0 ? s0 : ch.l0;
    ch.S1 += ch.l1 * s1;
    ch.f1  = ch.f1 ? ch.f1 : s1;
    ch.l1  = s1 ? s1 : ch.l1;
}

__global__ void __launch_bounds__(NTHR, 4) fused_loss(
    const float* __restrict__ x, const int* __restrict__ tg,
    float* __restrict__ out, int B, int rpw, float c30_1)
{
    const int lane = threadIdx.x & 31;
    const int warp = threadIdx.x >> 5;
    const int tid  = threadIdx.x;

    long long wbase = ((long long)blockIdx.x * NWARP + warp) * (long long)rpw;
    const float4* x4 = (const float4*)x;
    const int4*   t4 = (const int4*)tg;

    float lsum = 0.f, fsum = 0.f;
    int n1 = 0;
    Chain wacc = {0, 0, 0, 0, 0, 0};

    const int iters = rpw >> 7;                 // 128 rows per warp-iteration
    for (int j = 0; j < iters; ++j) {
        long long row_ll = wbase + (long long)j * 128 + lane * 4;
        Chain seg = {0, 0, 0, 0, 0, 0};
        if (row_ll + 3 < (long long)B) {
            int row = (int)row_ll;
            float4 xa = x4[row >> 1];
            float4 xb = x4[(row >> 1) + 1];
            int4   tt = t4[row >> 2];
            row_op(xa.x, xa.y, tt.x, c30_1, lsum, fsum, n1, seg);
            row_op(xa.z, xa.w, tt.y, c30_1, lsum, fsum, n1, seg);
            row_op(xb.x, xb.y, tt.z, c30_1, lsum, fsum, n1, seg);
            row_op(xb.z, xb.w, tt.w, c30_1, lsum, fsum, n1, seg);
        } else if (row_ll < (long long)B) {
            for (int k = 0; k < 4; ++k) {
                long long r = row_ll + k;
                if (r < (long long)B)
                    row_op(x[2 * r], x[2 * r + 1], tg[(int)r], c30_1, lsum, fsum, n1, seg);
            }
        }
        // O(1) ordered warp combine per class (ballot + 3 shfl + REDUX)
        int F0, L0, S0, F1, L1, S1;
        warp_chain(seg.f0, seg.l0, seg.S0, lane, F0, L0, S0);
        warp_chain(seg.f1, seg.l1, seg.S1, lane, F1, L1, S1);
        // warp-uniform values: every lane maintains wacc redundantly (no divergence)
        wacc.S0 += S0 + wacc.l0 * F0;
        wacc.f0  = wacc.f0 ? wacc.f0 : F0;
        wacc.l0  = L0 ? L0 : wacc.l0;
        wacc.S1 += S1 + wacc.l1 * F1;
        wacc.f1  = wacc.f1 ? wacc.f1 : F1;
        wacc.l1  = L1 ? L1 : wacc.l1;
    }

    // scalar reductions across warp (fixed tree -> deterministic)
    #pragma unroll
    for (int off = 16; off; off >>= 1) {
        lsum += __shfl_down_sync(0xffffffffu, lsum, off);
        fsum += __shfl_down_sync(0xffffffffu, fsum, off);
    }
    n1 = __reduce_add_sync(0xffffffffu, n1);

    __shared__ Chain smon[NWARP];
    __shared__ float sls[NWARP], sfs[NWARP];
    __shared__ int   sn1[NWARP];
    if (lane == 0) { smon[warp] = wacc; sls[warp] = lsum; sfs[warp] = fsum; sn1[warp] = n1; }
    __syncthreads();
    if (tid == 0) {
        Chain c = smon[0];
        float fl = sls[0], ff = sfs[0];
        int nn = sn1[0];
        for (int w = 1; w < NWARP; ++w) {
            c = chain_combine(c, smon[w]);
            fl += sls[w]; ff += sfs[w]; nn += sn1[w];
        }
        g_l[blockIdx.x]  = fl;
        g_f[blockIdx.x]  = ff;
        g_n1[blockIdx.x] = nn;
        int* m = g_c[blockIdx.x];
        m[0] = c.f0; m[1] = c.l0; m[2] = c.S0;
        m[3] = c.f1; m[4] = c.l1; m[5] = c.S1;
    }

    // ---- last-block final reduction (fused "pass2") ----
    __shared__ unsigned s_last;
    if (tid == 0) {
        __threadfence();
        unsigned r = atomicAdd(&g_count, 1u);
        s_last = (r == (unsigned)(gridDim.x - 1));
    }
    __syncthreads();
    if (!s_last) return;
    __threadfence();

    const int CH = (GRID + NTHR - 1) / NTHR;    // 3 consecutive partials per thread
    Chain c = {0, 0, 0, 0, 0, 0};
    double dl = 0.0, df = 0.0;
    long long nn = 0;
    #pragma unroll
    for (int k = 0; k < CH; ++k) {
        int i = tid * CH + k;                   // contiguous per-thread chunk, in order
        if (i < GRID) {
            const int* m = g_c[i];
            Chain b = {m[0], m[1], m[2], m[3], m[4], m[5]};
            c = chain_combine(c, b);
            dl += (double)g_l[i]; df += (double)g_f[i]; nn += g_n1[i];
        }
    }
    // ordered combine across the 32 lanes of each warp
    int F0, L0, S0, F1, L1, S1;
    warp_chain(c.f0, c.l0, c.S0, lane, F0, L0, S0);
    warp_chain(c.f1, c.l1, c.S1, lane, F1, L1, S1);
    #pragma unroll
    for (int off = 16; off; off >>= 1) {
        dl += __shfl_down_sync(0xffffffffu, dl, off);
        df += __shfl_down_sync(0xffffffffu, df, off);
        nn += __shfl_down_sync(0xffffffffu, nn, off);
    }

    __shared__ Chain s2mon[NWARP];
    __shared__ double s2l[NWARP], s2f[NWARP];
    __shared__ long long s2n[NWARP];
    if (lane == 0) {
        Chain wc = {F0, L0, S0, F1, L1, S1};
        s2mon[warp] = wc; s2l[warp] = dl; s2f[warp] = df; s2n[warp] = nn;
    }
    __syncthreads();
    if (tid == 0) {
        Chain t = s2mon[0];
        double tl = s2l[0], tf = s2f[0];
        long long tn = s2n[0];
        for (int w = 1; w < NWARP; ++w) {
            t = chain_combine(t, s2mon[w]);
            tl += s2l[w]; tf += s2f[w]; tn += s2n[w];
        }
        long long n1t = tn;
        long long n0t = (long long)B - n1t;
        double W     = 0.15 * (double)n0t + 0.85 * (double)n1t;
        double ldam  = tl / W;
        double focal = tf / (double)B;
        double p0 = (n0t > 0) ? (double)t.S0 / (double)n0t : 0.0;
        double p1 = (n1t > 0) ? (double)t.S1 / (double)n1t : 0.0;
        double dp = p0 - p1;
        out[0] = (float)(ldam + focal + dp * dp);
        __threadfence();
        g_count = 0;                           // reset for next graph replay
    }
}

extern "C" void kernel_launch(void* const* d_in, const int* in_sizes, int n_in,
                              void* d_out, int out_size)
{
    const float* x  = (const float*)d_in[0];
    const int*   tg = (const int*)d_in[1];
    int B = in_sizes[1];

    // rows per warp, multiple of 128 (one warp-iteration)
    int rpw = (B + GRID * NWARP - 1) / (GRID * NWARP);
    rpw = (rpw + 127) & ~127;

    float c30_1 = (float)(30.0 * 0.5 * pow(85.0 / 900.0, 0.25));

    fused_loss<<<GRID, NTHR>>>(x, tg, (float*)d_out, B, rpw, c30_1);
}

// round 3
// speedup vs baseline: 1.4235x; 1.2397x over previous
#include <cuda_runtime.h>
#include <math.h>

#define GRID  592            // 148 SMs * 4 blocks -> one wave at 256thr/<=64reg
#define NTHR  256
#define NWARP (NTHR / 32)

#define K2F   43.28085122666891f    // 30*log2(e)
#define C0F   21.640425613334455f   // 15*log2(e)
#define LN2D  0.6931471805599453

__device__ __forceinline__ float ex2f(float x){ float r; asm("ex2.approx.ftz.f32 %0, %1;" : "=f"(r) : "f"(x)); return r; }
__device__ __forceinline__ float lg2f(float x){ float r; asm("lg2.approx.ftz.f32 %0, %1;" : "=f"(r) : "f"(x)); return r; }

struct Chain { int f0, l0, S0, f1, l1, S1; };

__device__ __forceinline__ Chain chain_combine(const Chain& a, const Chain& b) {
    Chain r;
    r.S0 = a.S0 + b.S0 + a.l0 * b.f0;
    r.S1 = a.S1 + b.S1 + a.l1 * b.f1;
    r.f0 = a.f0 ? a.f0 : b.f0;
    r.f1 = a.f1 ? a.f1 : b.f1;
    r.l0 = b.l0 ? b.l0 : a.l0;
    r.l1 = b.l1 ? b.l1 : a.l1;
    return r;
}

// Ballot-based ordered combine of 32 lane-chains (one class) in O(1).
__device__ __forceinline__ void warp_chain(int f, int l, int S, int lane,
                                           int& Fw, int& Lw, int& Sw)
{
    unsigned m     = __ballot_sync(0xffffffffu, f != 0);
    unsigned below = m & ((1u << lane) - 1u);
    int prev_l = __shfl_sync(0xffffffffu, l, below ? (31 - __clz(below)) : 0);
    int term   = (f != 0 && below) ? prev_l * f : 0;
    Sw = __reduce_add_sync(0xffffffffu, S + term);
    int fsrc = m ? (__ffs(m) - 1) : 0;
    int lsrc = m ? (31 - __clz(m)) : 0;
    Fw = __shfl_sync(0xffffffffu, f, fsrc);
    Lw = __shfl_sync(0xffffffffu, l, lsrc);
    if (!m) { Fw = 0; Lw = 0; }
}

__device__ float    g_l[GRID];
__device__ float    g_f[GRID];
__device__ int      g_n1[GRID];
__device__ int      g_c[GRID][6];
__device__ unsigned g_count = 0;   // reset by last block each run (replay-safe)

// Per-row work, log2 domain. lsum accumulates w*nll2 (nll2 = softplus(a)/ln2),
// fsum accumulates w*sq*lg2(la+eps)  (final: focal = -ln2 * fsum / B).
__device__ __forceinline__ void row_op(float x0, float x1, int t, float c1,
                                       float& lsum, float& fsum, int& n1c,
                                       int& l0, int& l1, int& S0, int& S1,
                                       int& f0, int& f1)
{
    float d  = x0 - x1;
    bool  t1 = (t != 0);

    float sd  = t1 ? d : -d;
    float c   = t1 ? c1 : C0F;
    float a2  = fmaf(K2F, sd, c);
    float nll2 = lg2f(1.0f + ex2f(a2));
    float w   = t1 ? 0.85f : 0.15f;
    lsum = fmaf(w, nll2, lsum);

    float one  = 1.0f - x1;
    float la   = t1 ? x1 : one;
    float omla = t1 ? one : x1;
    float sq   = omla * omla;
    float lg   = lg2f(la + 1e-9f);
    fsum = fmaf(w * sq, lg, fsum);

    n1c += (int)t1;

    int s  = (d > 0.0f) ? 1 : -1;
    int s0 = t1 ? 0 : s;
    int s1 = t1 ? s : 0;
    S0 += l0 * s0;
    f0  = f0 ? f0 : s0;
    l0  = t1 ? l0 : s;
    S1 += l1 * s1;
    f1  = f1 ? f1 : s1;
    l1  = t1 ? s : l1;
}

__global__ void __launch_bounds__(NTHR, 4) fused_loss(
    const float* __restrict__ x, const int* __restrict__ tg,
    float* __restrict__ out, int B, int rpw, float c1)
{
    const int lane = threadIdx.x & 31;
    const int warp = threadIdx.x >> 5;
    const int tid  = threadIdx.x;

    long long wbase = ((long long)blockIdx.x * NWARP + warp) * (long long)rpw;
    const float4* x4 = (const float4*)x;
    const int4*   t4 = (const int4*)tg;

    float lsum = 0.f, fsum = 0.f;
    int n1 = 0;
    Chain wacc = {0, 0, 0, 0, 0, 0};

    const int iters = rpw >> 8;                 // 256 rows per warp-iteration
    for (int j = 0; j < iters; ++j) {
        long long row_ll = wbase + (long long)j * 256 + lane * 8;
        int l0 = 0, l1 = 0, S0 = 0, S1 = 0, f0 = 0, f1 = 0;
        if (row_ll + 7 < (long long)B) {
            int row = (int)row_ll;
            const float4* px = x4 + (row >> 1);
            float4 xa = __ldcs(px + 0);
            float4 xb = __ldcs(px + 1);
            float4 xc = __ldcs(px + 2);
            float4 xd = __ldcs(px + 3);
            int4   ta = __ldcs(t4 + (row >> 2));
            int4   tb = __ldcs(t4 + (row >> 2) + 1);
            row_op(xa.x, xa.y, ta.x, c1, lsum, fsum, n1, l0, l1, S0, S1, f0, f1);
            row_op(xa.z, xa.w, ta.y, c1, lsum, fsum, n1, l0, l1, S0, S1, f0, f1);
            row_op(xb.x, xb.y, ta.z, c1, lsum, fsum, n1, l0, l1, S0, S1, f0, f1);
            row_op(xb.z, xb.w, ta.w, c1, lsum, fsum, n1, l0, l1, S0, S1, f0, f1);
            row_op(xc.x, xc.y, tb.x, c1, lsum, fsum, n1, l0, l1, S0, S1, f0, f1);
            row_op(xc.z, xc.w, tb.y, c1, lsum, fsum, n1, l0, l1, S0, S1, f0, f1);
            row_op(xd.x, xd.y, tb.z, c1, lsum, fsum, n1, l0, l1, S0, S1, f0, f1);
            row_op(xd.z, xd.w, tb.w, c1, lsum, fsum, n1, l0, l1, S0, S1, f0, f1);
        } else if (row_ll < (long long)B) {
            for (int k = 0; k < 8; ++k) {
                long long r = row_ll + k;
                if (r < (long long)B)
                    row_op(x[2 * r], x[2 * r + 1], tg[(int)r], c1,
                           lsum, fsum, n1, l0, l1, S0, S1, f0, f1);
            }
        }
        // O(1) ordered warp combine per class
        int F0, L0, Sw0, F1, L1, Sw1;
        warp_chain(f0, l0, S0, lane, F0, L0, Sw0);
        warp_chain(f1, l1, S1, lane, F1, L1, Sw1);
        wacc.S0 += Sw0 + wacc.l0 * F0;
        wacc.f0  = wacc.f0 ? wacc.f0 : F0;
        wacc.l0  = L0 ? L0 : wacc.l0;
        wacc.S1 += Sw1 + wacc.l1 * F1;
        wacc.f1  = wacc.f1 ? wacc.f1 : F1;
        wacc.l1  = L1 ? L1 : wacc.l1;
    }

    #pragma unroll
    for (int off = 16; off; off >>= 1) {
        lsum += __shfl_down_sync(0xffffffffu, lsum, off);
        fsum += __shfl_down_sync(0xffffffffu, fsum, off);
    }
    n1 = __reduce_add_sync(0xffffffffu, n1);

    __shared__ Chain smon[NWARP];
    __shared__ float sls[NWARP], sfs[NWARP];
    __shared__ int   sn1[NWARP];
    if (lane == 0) { smon[warp] = wacc; sls[warp] = lsum; sfs[warp] = fsum; sn1[warp] = n1; }
    __syncthreads();
    if (tid == 0) {
        Chain c = smon[0];
        float fl = sls[0], ff = sfs[0];
        int nn = sn1[0];
        for (int w = 1; w < NWARP; ++w) {
            c = chain_combine(c, smon[w]);
            fl += sls[w]; ff += sfs[w]; nn += sn1[w];
        }
        g_l[blockIdx.x]  = fl;
        g_f[blockIdx.x]  = ff;
        g_n1[blockIdx.x] = nn;
        int* m = g_c[blockIdx.x];
        m[0] = c.f0; m[1] = c.l0; m[2] = c.S0;
        m[3] = c.f1; m[4] = c.l1; m[5] = c.S1;
    }

    // ---- last-block final reduction ----
    __shared__ unsigned s_last;
    if (tid == 0) {
        __threadfence();
        unsigned r = atomicAdd(&g_count, 1u);
        s_last = (r == (unsigned)(gridDim.x - 1));
    }
    __syncthreads();
    if (!s_last) return;
    __threadfence();

    const int CH = (GRID + NTHR - 1) / NTHR;
    Chain c = {0, 0, 0, 0, 0, 0};
    double dl = 0.0, df = 0.0;
    long long nn = 0;
    #pragma unroll
    for (int k = 0; k < CH; ++k) {
        int i = tid * CH + k;
        if (i < GRID) {
            const int* m = g_c[i];
            Chain b = {m[0], m[1], m[2], m[3], m[4], m[5]};
            c = chain_combine(c, b);
            dl += (double)g_l[i]; df += (double)g_f[i]; nn += g_n1[i];
        }
    }
    int F0, L0, S0, F1, L1, S1;
    warp_chain(c.f0, c.l0, c.S0, lane, F0, L0, S0);
    warp_chain(c.f1, c.l1, c.S1, lane, F1, L1, S1);
    #pragma unroll
    for (int off = 16; off; off >>= 1) {
        dl += __shfl_down_sync(0xffffffffu, dl, off);
        df += __shfl_down_sync(0xffffffffu, df, off);
        nn += __shfl_down_sync(0xffffffffu, nn, off);
    }

    __shared__ Chain s2mon[NWARP];
    __shared__ double s2l[NWARP], s2f[NWARP];
    __shared__ long long s2n[NWARP];
    if (lane == 0) {
        Chain wc = {F0, L0, S0, F1, L1, S1};
        s2mon[warp] = wc; s2l[warp] = dl; s2f[warp] = df; s2n[warp] = nn;
    }
    __syncthreads();
    if (tid == 0) {
        Chain t = s2mon[0];
        double tl = s2l[0], tf = s2f[0];
        long long tn = s2n[0];
        for (int w = 1; w < NWARP; ++w) {
            t = chain_combine(t, s2mon[w]);
            tl += s2l[w]; tf += s2f[w]; tn += s2n[w];
        }
        long long n1t = tn;
        long long n0t = (long long)B - n1t;
        double W     = 0.15 * (double)n0t + 0.85 * (double)n1t;
        double ldam  = LN2D * tl / W;
        double focal = -LN2D * tf / (double)B;
        double p0 = (n0t > 0) ? (double)t.S0 / (double)n0t : 0.0;
        double p1 = (n1t > 0) ? (double)t.S1 / (double)n1t : 0.0;
        double dp = p0 - p1;
        out[0] = (float)(ldam + focal + dp * dp);
        __threadfence();
        g_count = 0;
    }
}

extern "C" void kernel_launch(void* const* d_in, const int* in_sizes, int n_in,
                              void* d_out, int out_size)
{
    const float* x  = (const float*)d_in[0];
    const int*   tg = (const int*)d_in[1];
    int B = in_sizes[1];

    // rows per warp, multiple of 256 (one warp-iteration)
    int wtot = GRID * NWARP;
    int rpw = (B + wtot - 1) / wtot;
    rpw = (rpw + 255) & ~255;

    // class-1 LDAM margin * 30 * log2(e)
    float c1 = (float)(30.0 * 0.5 * pow(85.0 / 900.0, 0.25) * 1.4426950408889634);

    fused_loss<<<GRID, NTHR>>>(x, tg, (float*)d_out, B, rpw, c1);
}

// round 4
// speedup vs baseline: 1.4734x; 1.0350x over previous
#include <cuda_runtime.h>
#include <math.h>

#define GRID  592            // 148 SMs * 4 blocks -> one wave at 256thr/<=64reg
#define NTHR  256
#define NWARP (NTHR / 32)

#define K2F   43.28085122666891f    // 30*log2(e)
#define C0F   21.640425613334455f   // 15*log2(e)
#define LN2D  0.6931471805599453

__device__ __forceinline__ float ex2f(float x){ float r; asm("ex2.approx.ftz.f32 %0, %1;" : "=f"(r) : "f"(x)); return r; }
__device__ __forceinline__ float lg2f(float x){ float r; asm("lg2.approx.ftz.f32 %0, %1;" : "=f"(r) : "f"(x)); return r; }

struct Chain { int f0, l0, S0, f1, l1, S1; };

__device__ __forceinline__ Chain chain_combine(const Chain& a, const Chain& b) {
    Chain r;
    r.S0 = a.S0 + b.S0 + a.l0 * b.f0;
    r.S1 = a.S1 + b.S1 + a.l1 * b.f1;
    r.f0 = a.f0 ? a.f0 : b.f0;
    r.f1 = a.f1 ? a.f1 : b.f1;
    r.l0 = b.l0 ? b.l0 : a.l0;
    r.l1 = b.l1 ? b.l1 : a.l1;
    return r;
}

// Ballot-based ordered combine of 32 lane-chains (one class) in O(1).
__device__ __forceinline__ void warp_chain(int f, int l, int S, int lane,
                                           int& Fw, int& Lw, int& Sw)
{
    unsigned m     = __ballot_sync(0xffffffffu, f != 0);
    unsigned below = m & ((1u << lane) - 1u);
    int prev_l = __shfl_sync(0xffffffffu, l, below ? (31 - __clz(below)) : 0);
    int term   = (f != 0 && below) ? prev_l * f : 0;
    Sw = __reduce_add_sync(0xffffffffu, S + term);
    int fsrc = m ? (__ffs(m) - 1) : 0;
    int lsrc = m ? (31 - __clz(m)) : 0;
    Fw = __shfl_sync(0xffffffffu, f, fsrc);
    Lw = __shfl_sync(0xffffffffu, l, lsrc);
    if (!m) { Fw = 0; Lw = 0; }
}

__device__ float    g_l[GRID];
__device__ float    g_f[GRID];
__device__ int      g_n1[GRID];
__device__ int      g_c[GRID][6];
__device__ unsigned g_count = 0;   // reset by last block each run (replay-safe)

// Per-row work, log2 domain, predication-friendly.
// lsum1/lsum0 accumulate nll2 per class; fsum1/fsum0 accumulate sq*lg per class.
__device__ __forceinline__ void row_op(float x0, float x1, int t, float c1,
                                       float& ls0, float& ls1,
                                       float& fs0, float& fs1, int& n1c,
                                       int& l0, int& l1, int& S0, int& S1,
                                       int& f0, int& f1)
{
    float d = x0 - x1;
    bool  P = (t != 0);

    float a2 = P ? fmaf(K2F, d, c1) : fmaf(-K2F, d, C0F);
    float nl = lg2f(1.0f + ex2f(a2));
    if (P) ls1 += nl; else ls0 += nl;

    float one = 1.0f - x1;
    float la  = P ? x1 : one;
    float om  = 1.0f - la;
    float lg  = lg2f(la + 1e-9f);
    float sq  = om * om;
    if (P) fs1 = fmaf(sq, lg, fs1); else fs0 = fmaf(sq, lg, fs0);

    n1c += t;

    int s = (__float_as_int(d) >> 31) | 1;     // d<0 -> -1 else +1
    if (P) { S1 += l1 * s; f1 = f1 ? f1 : s; l1 = s; }
    else   { S0 += l0 * s; f0 = f0 ? f0 : s; l0 = s; }
}

__global__ void __launch_bounds__(NTHR, 4) fused_loss(
    const float* __restrict__ x, const int* __restrict__ tg,
    float* __restrict__ out, int B, int rpw, float c1)
{
    const int lane = threadIdx.x & 31;
    const int warp = threadIdx.x >> 5;
    const int tid  = threadIdx.x;

    long long wbase = ((long long)blockIdx.x * NWARP + warp) * (long long)rpw;

    float ls0 = 0.f, ls1 = 0.f, fs0 = 0.f, fs1 = 0.f;
    int n1 = 0;
    Chain wacc = {0, 0, 0, 0, 0, 0};

    const int iters = rpw >> 8;                 // 256 rows per warp-iteration

    if (wbase + (long long)rpw <= (long long)B) {
        // -------- full path: no bounds checks, pointer bumping --------
        const float4* px = (const float4*)x  + ((wbase + lane * 8) >> 1);
        const int4*   pt = (const int4*)tg + ((wbase + lane * 8) >> 2);
        for (int j = 0; j < iters; ++j) {
            float4 xa = __ldcs(px + 0);
            float4 xb = __ldcs(px + 1);
            float4 xc = __ldcs(px + 2);
            float4 xd = __ldcs(px + 3);
            int4   ta = __ldcs(pt + 0);
            int4   tb = __ldcs(pt + 1);
            px += 128;  pt += 64;               // 256 rows forward
            int l0 = 0, l1 = 0, S0 = 0, S1 = 0, f0 = 0, f1 = 0;
            row_op(xa.x, xa.y, ta.x, c1, ls0, ls1, fs0, fs1, n1, l0, l1, S0, S1, f0, f1);
            row_op(xa.z, xa.w, ta.y, c1, ls0, ls1, fs0, fs1, n1, l0, l1, S0, S1, f0, f1);
            row_op(xb.x, xb.y, ta.z, c1, ls0, ls1, fs0, fs1, n1, l0, l1, S0, S1, f0, f1);
            row_op(xb.z, xb.w, ta.w, c1, ls0, ls1, fs0, fs1, n1, l0, l1, S0, S1, f0, f1);
            row_op(xc.x, xc.y, tb.x, c1, ls0, ls1, fs0, fs1, n1, l0, l1, S0, S1, f0, f1);
            row_op(xc.z, xc.w, tb.y, c1, ls0, ls1, fs0, fs1, n1, l0, l1, S0, S1, f0, f1);
            row_op(xd.x, xd.y, tb.z, c1, ls0, ls1, fs0, fs1, n1, l0, l1, S0, S1, f0, f1);
            row_op(xd.z, xd.w, tb.w, c1, ls0, ls1, fs0, fs1, n1, l0, l1, S0, S1, f0, f1);
            int F0, L0, Sw0, F1, L1, Sw1;
            warp_chain(f0, l0, S0, lane, F0, L0, Sw0);
            warp_chain(f1, l1, S1, lane, F1, L1, Sw1);
            wacc.S0 += Sw0 + wacc.l0 * F0;
            wacc.f0  = wacc.f0 ? wacc.f0 : F0;
            wacc.l0  = L0 ? L0 : wacc.l0;
            wacc.S1 += Sw1 + wacc.l1 * F1;
            wacc.f1  = wacc.f1 ? wacc.f1 : F1;
            wacc.l1  = L1 ? L1 : wacc.l1;
        }
    } else if (wbase < (long long)B) {
        // -------- tail path (at most one warp strip crosses B) --------
        for (int j = 0; j < iters; ++j) {
            long long base = wbase + (long long)j * 256;
            if (base >= (long long)B) break;
            long long row0 = base + lane * 8;
            int l0 = 0, l1 = 0, S0 = 0, S1 = 0, f0 = 0, f1 = 0;
            for (int k = 0; k < 8; ++k) {
                long long r = row0 + k;
                if (r < (long long)B)
                    row_op(x[2 * r], x[2 * r + 1], tg[(int)r], c1,
                           ls0, ls1, fs0, fs1, n1, l0, l1, S0, S1, f0, f1);
            }
            int F0, L0, Sw0, F1, L1, Sw1;
            warp_chain(f0, l0, S0, lane, F0, L0, Sw0);
            warp_chain(f1, l1, S1, lane, F1, L1, Sw1);
            wacc.S0 += Sw0 + wacc.l0 * F0;
            wacc.f0  = wacc.f0 ? wacc.f0 : F0;
            wacc.l0  = L0 ? L0 : wacc.l0;
            wacc.S1 += Sw1 + wacc.l1 * F1;
            wacc.f1  = wacc.f1 ? wacc.f1 : F1;
            wacc.l1  = L1 ? L1 : wacc.l1;
        }
    }

    // fold class weights, then commutative warp reductions
    float lsum = fmaf(0.85f, ls1, 0.15f * ls0);
    float fsum = fmaf(0.85f, fs1, 0.15f * fs0);
    #pragma unroll
    for (int off = 16; off; off >>= 1) {
        lsum += __shfl_down_sync(0xffffffffu, lsum, off);
        fsum += __shfl_down_sync(0xffffffffu, fsum, off);
    }
    n1 = __reduce_add_sync(0xffffffffu, n1);

    __shared__ Chain smon[NWARP];
    __shared__ float sls[NWARP], sfs[NWARP];
    __shared__ int   sn1[NWARP];
    if (lane == 0) { smon[warp] = wacc; sls[warp] = lsum; sfs[warp] = fsum; sn1[warp] = n1; }
    __syncthreads();
    if (tid == 0) {
        Chain c = smon[0];
        float fl = sls[0], ff = sfs[0];
        int nn = sn1[0];
        for (int w = 1; w < NWARP; ++w) {
            c = chain_combine(c, smon[w]);
            fl += sls[w]; ff += sfs[w]; nn += sn1[w];
        }
        g_l[blockIdx.x]  = fl;
        g_f[blockIdx.x]  = ff;
        g_n1[blockIdx.x] = nn;
        int* m = g_c[blockIdx.x];
        m[0] = c.f0; m[1] = c.l0; m[2] = c.S0;
        m[3] = c.f1; m[4] = c.l1; m[5] = c.S1;
    }

    // ---- last-block final reduction ----
    __shared__ unsigned s_last;
    if (tid == 0) {
        __threadfence();
        unsigned r = atomicAdd(&g_count, 1u);
        s_last = (r == (unsigned)(gridDim.x - 1));
    }
    __syncthreads();
    if (!s_last) return;
    __threadfence();

    const int CH = (GRID + NTHR - 1) / NTHR;
    Chain c = {0, 0, 0, 0, 0, 0};
    double dl = 0.0, df = 0.0;
    long long nn = 0;
    #pragma unroll
    for (int k = 0; k < CH; ++k) {
        int i = tid * CH + k;
        if (i < GRID) {
            const int* m = g_c[i];
            Chain b = {m[0], m[1], m[2], m[3], m[4], m[5]};
            c = chain_combine(c, b);
            dl += (double)g_l[i]; df += (double)g_f[i]; nn += g_n1[i];
        }
    }
    int F0, L0, S0, F1, L1, S1;
    warp_chain(c.f0, c.l0, c.S0, lane, F0, L0, S0);
    warp_chain(c.f1, c.l1, c.S1, lane, F1, L1, S1);
    #pragma unroll
    for (int off = 16; off; off >>= 1) {
        dl += __shfl_down_sync(0xffffffffu, dl, off);
        df += __shfl_down_sync(0xffffffffu, df, off);
        nn += __shfl_down_sync(0xffffffffu, nn, off);
    }

    __shared__ Chain s2mon[NWARP];
    __shared__ double s2l[NWARP], s2f[NWARP];
    __shared__ long long s2n[NWARP];
    if (lane == 0) {
        Chain wc = {F0, L0, S0, F1, L1, S1};
        s2mon[warp] = wc; s2l[warp] = dl; s2f[warp] = df; s2n[warp] = nn;
    }
    __syncthreads();
    if (tid == 0) {
        Chain t = s2mon[0];
        double tl = s2l[0], tf = s2f[0];
        long long tn = s2n[0];
        for (int w = 1; w < NWARP; ++w) {
            t = chain_combine(t, s2mon[w]);
            tl += s2l[w]; tf += s2f[w]; tn += s2n[w];
        }
        long long n1t = tn;
        long long n0t = (long long)B - n1t;
        double W     = 0.15 * (double)n0t + 0.85 * (double)n1t;
        double ldam  = LN2D * tl / W;
        double focal = -LN2D * tf / (double)B;
        double p0 = (n0t > 0) ? (double)t.S0 / (double)n0t : 0.0;
        double p1 = (n1t > 0) ? (double)t.S1 / (double)n1t : 0.0;
        double dp = p0 - p1;
        out[0] = (float)(ldam + focal + dp * dp);
        __threadfence();
        g_count = 0;
    }
}

extern "C" void kernel_launch(void* const* d_in, const int* in_sizes, int n_in,
                              void* d_out, int out_size)
{
    const float* x  = (const float*)d_in[0];
    const int*   tg = (const int*)d_in[1];
    int B = in_sizes[1];

    // rows per warp, multiple of 256 (one warp-iteration)
    int wtot = GRID * NWARP;
    int rpw = (B + wtot - 1) / wtot;
    rpw = (rpw + 255) & ~255;

    // class-1 LDAM margin * 30 * log2(e)
    float c1 = (float)(30.0 * 0.5 * pow(85.0 / 900.0, 0.25) * 1.4426950408889634);

    fused_loss<<<GRID, NTHR>>>(x, tg, (float*)d_out, B, rpw, c1);
}